// round 16
// baseline (speedup 1.0000x reference)
#include <cuda_runtime.h>
#include <math_constants.h>

// Problem shapes (from reference setup_inputs)
#define B_DIM 8
#define C_IN 32
#define C_OUT 32
#define P_DIM 262144
#define K_SH 81                         // (MAX_L+1)^2, MAX_L=8
#define N_ROWS (B_DIM * C_IN)           // 256
#define SPLITS 4
#define CHUNK (P_DIM / SPLITS)          // 65536 elements per block (256 KB)
#define THREADS 256
#define N_RED_BLOCKS (N_ROWS * SPLITS)  // 1024
#define N_M0 9                          // k values with m == 0 (l = 0..8)

// Scratch (no cudaMalloc allowed)
__device__ float g_partials[N_RED_BLOCKS];

// ---------------------------------------------------------------------------
// Phase 1: streaming reduce (R11 configuration: natural registers, NO
// min-blocks bound — R13/R14 proved any reg cap spills the hot loop).
// NEW vs R11: blocks 0..80 write the 256 zeros of their k first when m != 0
// (one predicated store per thread; registers dead before the stream starts;
// cost hidden under the 40us stream). PDL trigger at block start only gates
// the epilogue's LAUNCH; data safety is griddepcontrol in the epilogue.
// ---------------------------------------------------------------------------
__global__ void __launch_bounds__(THREADS) reduce_kernel(
        const float* __restrict__ in, float* __restrict__ out) {
    cudaTriggerProgrammaticLaunchCompletion();

    // Zero-write prologue for the 72 m != 0 coefficient slots.
    if (blockIdx.x < K_SH) {
        const int k = blockIdx.x;
        int l = 0;
        while ((l + 1) * (l + 1) <= k) ++l;
        if (k != l * l + l)                        // m != 0
            out[(size_t)threadIdx.x * K_SH + k] = 0.0f;
    }

    const int row   = blockIdx.x / SPLITS;
    const int split = blockIdx.x % SPLITS;
    const float4* __restrict__ p =
        reinterpret_cast<const float4*>(in + (size_t)row * P_DIM + (size_t)split * CHUNK);

    float a0 = 0.f, a1 = 0.f, a2 = 0.f, a3 = 0.f;
    #pragma unroll 4
    for (int jo = 0; jo < 16; ++jo) {
        float4 v0 = __ldcs(&p[threadIdx.x + (jo * 4 + 0) * THREADS]);
        float4 v1 = __ldcs(&p[threadIdx.x + (jo * 4 + 1) * THREADS]);
        float4 v2 = __ldcs(&p[threadIdx.x + (jo * 4 + 2) * THREADS]);
        float4 v3 = __ldcs(&p[threadIdx.x + (jo * 4 + 3) * THREADS]);
        a0 += (v0.x + v0.y) + (v0.z + v0.w);
        a1 += (v1.x + v1.y) + (v1.z + v1.w);
        a2 += (v2.x + v2.y) + (v2.z + v2.w);
        a3 += (v3.x + v3.y) + (v3.z + v3.w);
    }
    float acc = (a0 + a1) + (a2 + a3);

    #pragma unroll
    for (int off = 16; off > 0; off >>= 1)
        acc += __shfl_xor_sync(0xFFFFFFFFu, acc, off);

    __shared__ float warp_sums[THREADS / 32];
    const int lane = threadIdx.x & 31;
    const int wid  = threadIdx.x >> 5;
    if (lane == 0) warp_sums[wid] = acc;
    __syncthreads();

    if (wid == 0) {
        float s = (lane < THREADS / 32) ? warp_sums[lane] : 0.0f;
        #pragma unroll
        for (int off = 4; off > 0; off >>= 1)
            s += __shfl_xor_sync(0xFFFFFFFFu, s, off);
        if (lane == 0) g_partials[blockIdx.x] = s;
    }
}

// ---------------------------------------------------------------------------
// Phase 2 (PDL, 9 blocks — one per l with m == 0, k = l*l + l):
// launches while the reduce streams, stages coeff[:,:,k] into smem, parks at
// griddepcontrol.wait, then a short L2-hot fold + 32-FFMA dot + store.
// ---------------------------------------------------------------------------
__global__ void __launch_bounds__(B_DIM * C_OUT) epilogue_kernel(
        const float* __restrict__ coeff, float* __restrict__ out) {
    const int l = blockIdx.x;            // 0..8
    const int k = l * l + l;

    // Stage coeff[:,:,k] into smem while the primary grid still streams.
    __shared__ float s_coeff[C_OUT * C_IN];
    {
        float c0 = coeff[(size_t)(threadIdx.x + 0 * THREADS) * K_SH + k];
        float c1 = coeff[(size_t)(threadIdx.x + 1 * THREADS) * K_SH + k];
        float c2 = coeff[(size_t)(threadIdx.x + 2 * THREADS) * K_SH + k];
        float c3 = coeff[(size_t)(threadIdx.x + 3 * THREADS) * K_SH + k];
        s_coeff[threadIdx.x + 0 * THREADS] = c0;
        s_coeff[threadIdx.x + 1 * THREADS] = c1;
        s_coeff[threadIdx.x + 2 * THREADS] = c2;
        s_coeff[threadIdx.x + 3 * THREADS] = c3;
    }

    // HW wait for the primary grid (makes its g_partials stores visible).
    cudaGridDependencySynchronize();

    // Fold partials: thread t -> row t (L2-hit float4 load, fold in reg).
    __shared__ float s_rows[N_ROWS];
    {
        float4 pp = reinterpret_cast<const float4*>(g_partials)[threadIdx.x];
        s_rows[threadIdx.x] = (pp.x + pp.y) + (pp.z + pp.w);
    }
    __syncthreads();

    const int b = threadIdx.x / C_OUT;
    const int o = threadIdx.x % C_OUT;
    const float y = sqrtf((2.0f * l + 1.0f) / (4.0f * CUDART_PI_F));
    float acc = 0.0f;
    #pragma unroll
    for (int i = 0; i < C_IN; ++i)
        acc += s_coeff[o * C_IN + i] * s_rows[b * C_IN + i];
    out[((size_t)b * C_OUT + o) * K_SH + k] = y * acc;
}

// ---------------------------------------------------------------------------
extern "C" void kernel_launch(void* const* d_in, const int* in_sizes, int n_in,
                              void* d_out, int out_size) {
    const float* input = (const float*)d_in[0];   // [B, C_in, P]
    const float* coeff = (const float*)d_in[1];   // [C_out, C_in, K]
    float* out = (float*)d_out;                   // [B, C_out, K]

    reduce_kernel<<<N_RED_BLOCKS, THREADS>>>(input, out);

    cudaLaunchConfig_t cfg = {};
    cfg.gridDim  = dim3(N_M0, 1, 1);
    cfg.blockDim = dim3(B_DIM * C_OUT, 1, 1);
    cudaLaunchAttribute attrs[1];
    attrs[0].id = cudaLaunchAttributeProgrammaticStreamSerialization;
    attrs[0].val.programmaticStreamSerializationAllowed = 1;
    cfg.attrs = attrs;
    cfg.numAttrs = 1;
    cudaLaunchKernelEx(&cfg, epilogue_kernel, coeff, out);
}